// round 16
// baseline (speedup 1.0000x reference)
#include <cuda_runtime.h>
#include <math.h>

#define D     512
#define SLEN  4096
#define BATCH 4
#define CHK   64
#define NCH   64
#define NTOK  (BATCH*SLEN)
#define SCANR 256
#define BM 64
#define BN 64
#define BK 16
#define GRID_P 296

#define GSCALE   (2.0f/131072.0f)
#define DECAY    0.01f
#define LRATE    0.1f
#define MOMC     0.9f
#define EPS_RMS  1.1920929e-07f
#define EPS_L2   1e-12f

typedef unsigned long long ull;

// ---------------- scratch ----------------
__device__ float g_xs[NTOK*D];
__device__ float g_t [NTOK*D];       // prep temp; in scan reused as a0=silu(sum hp)
__device__ float g_k [NTOK*D];
__device__ float g_v [NTOK*D];
__device__ float g_q [NTOK*D];
__device__ float g_r [NTOK*D];
__device__ float g_cm[BATCH*NCH*D];
__device__ float g_gtmp[3*BATCH*NCH*D];
__device__ float g_gates[3*NCH];
__device__ float g_W0[D*D], g_m0[D*D], g_m1[D*D];
__device__ float g_W1d[2][D*D];      // double-buffered W1
__device__ float g_hp[4][D*D];       // split-K=4 partials of [k;q]@W0^T (512 rows)
__device__ float g_yp[4][D*D];       // split-K=4 partials of [a0;aq]@W1^T
__device__ float g_dap[4][SCANR*D];  // split-K=4 partials of dy@W1
__device__ float g_g1p[2][D*D];      // split-K=2 partials of gW1
__device__ float g_g0p[2][D*D];      // split-K=2 partials of gW0
__device__ unsigned g_barc = 0;
__device__ volatile unsigned g_barp = 0;

// ---------------- helpers ----------------
__device__ __forceinline__ float siluf(float v)  { return v/(1.0f+expf(-v)); }
__device__ __forceinline__ float sigf(float v)   { return 1.0f/(1.0f+expf(-v)); }
__device__ __forceinline__ float silupf(float v) { float s=1.0f/(1.0f+expf(-v)); return s*(1.0f+v*(1.0f-s)); }
__device__ __forceinline__ ull dup2(float x){ ull r; asm("mov.b64 %0,{%1,%1};":"=l"(r):"f"(x)); return r; }
__device__ __forceinline__ void fma2(ull &c, ull a, ull b){
  asm("fma.rn.f32x2 %0,%1,%2,%0;" : "+l"(c) : "l"(a), "l"(b));
}

__device__ __forceinline__ float blockReduce256(float v, float* red){
  int tid=threadIdx.x; red[tid]=v; __syncthreads();
  #pragma unroll
  for(int o=128;o>0;o>>=1){ if(tid<o) red[tid]+=red[tid+o]; __syncthreads(); }
  return red[0];
}

// grid-wide sense barrier (atomic counter; proven fastest in R11 vs flag design)
__device__ __forceinline__ void gsync(){
  __threadfence();
  __syncthreads();
  if(threadIdx.x==0){
    unsigned ph=g_barp;
    if(atomicAdd(&g_barc,1u)==gridDim.x-1u){
      g_barc=0; __threadfence(); g_barp=ph+1u;
    } else {
      while(g_barp==ph){ __nanosleep(32); }
    }
  }
  __syncthreads();
}

// ---------------- small kernels ----------------
__global__ void chunk_mean_k(const float* __restrict__ x){
  int rc=blockIdx.x; int b=rc>>6, t=rc&63; int d=threadIdx.x;
  const float* p=x+((size_t)b*SLEN+(size_t)t*CHK)*D+d;
  float s=0.f;
  #pragma unroll 8
  for(int c=0;c<CHK;c++) s+=p[(size_t)c*D];
  g_cm[(size_t)rc*D+d]=s*(1.0f/CHK);
}

__global__ void gate_reduce_k(){
  __shared__ float red[256];
  int t=blockIdx.x, g=blockIdx.y, tid=threadIdx.x;
  float s=0.f;
  for(int i=tid;i<BATCH*D;i+=256){
    int b=i>>9, e=i&511;
    s+=g_gtmp[((size_t)g*BATCH*NCH+(size_t)b*NCH+t)*D+e];
  }
  float tot=blockReduce256(s,red);
  if(tid==0){
    float sc=(g==0)?DECAY:((g==1)?LRATE:MOMC);
    g_gates[g*NCH+t]=sc*tot/(float)(BATCH*D);
  }
}

__global__ void rmsnorm_k(const float* __restrict__ x, const float* __restrict__ g,
                          float* __restrict__ outp){
  __shared__ float red[256];
  size_t base=(size_t)blockIdx.x*D; int tid=threadIdx.x;
  float v0=x[base+tid], v1=x[base+tid+256];
  float tot=blockReduce256(v0*v0+v1*v1,red);
  float r=rsqrtf(tot*(1.0f/D)+EPS_RMS);
  outp[base+tid]=v0*r*g[tid];
  outp[base+tid+256]=v1*r*g[tid+256];
}

__global__ void l2norm_k(float* __restrict__ p){
  __shared__ float red[256];
  size_t base=(size_t)blockIdx.x*D; int tid=threadIdx.x;
  float v0=p[base+tid], v1=p[base+tid+256];
  float tot=blockReduce256(v0*v0+v1*v1,red);
  float inv=1.0f/fmaxf(sqrtf(tot),EPS_L2);
  p[base+tid]=v0*inv; p[base+tid+256]=v1*inv;
}

__global__ void init_w_k(const float* __restrict__ memW){
  int i=blockIdx.x*256+threadIdx.x;
  g_W0[i]=memW[i]; g_W1d[0][i]=memW[D*D+i]; g_m0[i]=0.f; g_m1[i]=0.f;
}

// ---------------- scan GEMM core macros (4x4, single-buffer prefetch) ----------------
#define GEMM_VARS \
  const int tid=threadIdx.x; const int tx=tid&15, ty=tid>>4; \
  const int lr=tid>>2, lk=(tid&3)<<2; \
  const int kr=tid>>4, nc=(tid&15)<<2; \
  (void)lr;(void)lk;(void)kr;(void)nc;(void)tx;(void)ty;

#define FMA_TILE \
  _Pragma("unroll") \
  for(int kk=0;kk<BK;kk++){ \
    ull a01=*(const ull*)&As[kk][(ty<<2)]; \
    ull a23=*(const ull*)&As[kk][(ty<<2)+2]; \
    float4 bq=*(const float4*)&Bs[kk][(tx<<2)]; \
    ull b0=dup2(bq.x),b1=dup2(bq.y),b2=dup2(bq.z),b3=dup2(bq.w); \
    fma2(accp[0][0],a01,b0); fma2(accp[0][1],a01,b1); \
    fma2(accp[0][2],a01,b2); fma2(accp[0][3],a01,b3); \
    fma2(accp[1][0],a23,b0); fma2(accp[1][1],a23,b1); \
    fma2(accp[1][2],a23,b2); fma2(accp[1][3],a23,b3); \
  }

#define GEMM_UNPACK \
  float acc[4][4]; \
  _Pragma("unroll") \
  for(int j=0;j<4;j++){ \
    asm("mov.b64 {%0,%1},%2;":"=f"(acc[0][j]),"=f"(acc[1][j]):"l"(accp[0][j])); \
    asm("mov.b64 {%0,%1},%2;":"=f"(acc[2][j]),"=f"(acc[3][j]):"l"(accp[1][j])); \
  }

#define STS_A4(r4) { As[lk][lr]=r4.x; As[lk+1][lr]=r4.y; As[lk+2][lr]=r4.z; As[lk+3][lr]=r4.w; }
#define STS_B4(r4) { Bs[lk][lr]=r4.x; Bs[lk+1][lr]=r4.y; Bs[lk+2][lr]=r4.z; Bs[lk+3][lr]=r4.w; }
#define STS_AT4(r4){ As[kr][nc]=r4.x; As[kr][nc+1]=r4.y; As[kr][nc+2]=r4.z; As[kr][nc+3]=r4.w; }
#define STS_BT4(r4){ Bs[kr][nc]=r4.x; Bs[kr][nc+1]=r4.y; Bs[kr][nc+2]=r4.z; Bs[kr][nc+3]=r4.w; }

// ---------------- prep GEMMs: 4x8 microtile (BM=64, BN2=128), prefetched ----------------
#define BN2 128
#define FMA_TILE8 \
  _Pragma("unroll") \
  for(int kk=0;kk<BK;kk++){ \
    ull a01=*(const ull*)&As[kk][(ty<<2)]; \
    ull a23=*(const ull*)&As[kk][(ty<<2)+2]; \
    float4 bq0=*(const float4*)&Bs[kk][(tx<<3)]; \
    float4 bq1=*(const float4*)&Bs[kk][(tx<<3)+4]; \
    ull b0=dup2(bq0.x),b1=dup2(bq0.y),b2=dup2(bq0.z),b3=dup2(bq0.w); \
    ull b4=dup2(bq1.x),b5=dup2(bq1.y),b6=dup2(bq1.z),b7=dup2(bq1.w); \
    fma2(accp[0][0],a01,b0); fma2(accp[0][1],a01,b1); \
    fma2(accp[0][2],a01,b2); fma2(accp[0][3],a01,b3); \
    fma2(accp[0][4],a01,b4); fma2(accp[0][5],a01,b5); \
    fma2(accp[0][6],a01,b6); fma2(accp[0][7],a01,b7); \
    fma2(accp[1][0],a23,b0); fma2(accp[1][1],a23,b1); \
    fma2(accp[1][2],a23,b2); fma2(accp[1][3],a23,b3); \
    fma2(accp[1][4],a23,b4); fma2(accp[1][5],a23,b5); \
    fma2(accp[1][6],a23,b6); fma2(accp[1][7],a23,b7); \
  }

#define GEMM_UNPACK8 \
  float acc[4][8]; \
  _Pragma("unroll") \
  for(int j=0;j<8;j++){ \
    asm("mov.b64 {%0,%1},%2;":"=f"(acc[0][j]),"=f"(acc[1][j]):"l"(accp[0][j])); \
    asm("mov.b64 {%0,%1},%2;":"=f"(acc[2][j]),"=f"(acc[3][j]):"l"(accp[1][j])); \
  }

// C[M,512] = A[M,K] @ B[512,K]^T ; tile 64x128
__global__ void __launch_bounds__(256,2) gemm_nt(
    const float* __restrict__ A, const float* __restrict__ Bw,
    const float* __restrict__ bias, float* __restrict__ Cc, int K, int epi)
{
  __shared__ float As[BK][BM], Bs[BK][BN2];
  GEMM_VARS
  ull accp[2][8]={};
  const float* Ab=A +(size_t)blockIdx.y*BM*K;
  const float* Bb=Bw+(size_t)blockIdx.x*BN2*K;
  float4 ra =*(const float4*)(Ab+(size_t)lr*K+lk);
  float4 rb0=*(const float4*)(Bb+(size_t)lr*K+lk);
  float4 rb1=*(const float4*)(Bb+(size_t)(lr+64)*K+lk);
  const int KT=K/BK;
  for(int kt=0;kt<KT;kt++){
    STS_A4(ra)
    { Bs[lk][lr]=rb0.x; Bs[lk+1][lr]=rb0.y; Bs[lk+2][lr]=rb0.z; Bs[lk+3][lr]=rb0.w;
      Bs[lk][lr+64]=rb1.x; Bs[lk+1][lr+64]=rb1.y; Bs[lk+2][lr+64]=rb1.z; Bs[lk+3][lr+64]=rb1.w; }
    __syncthreads();
    if(kt+1<KT){
      int k0=(kt+1)*BK;
      ra =*(const float4*)(Ab+(size_t)lr*K+k0+lk);
      rb0=*(const float4*)(Bb+(size_t)lr*K+k0+lk);
      rb1=*(const float4*)(Bb+(size_t)(lr+64)*K+k0+lk);
    }
    FMA_TILE8
    __syncthreads();
  }
  GEMM_UNPACK8
  int rb2=blockIdx.y*BM+(ty<<2), cb=blockIdx.x*BN2+(tx<<3);
  #pragma unroll
  for(int i=0;i<4;i++)
    #pragma unroll
    for(int j=0;j<8;j++){
      float v=acc[i][j];
      if(epi==1) v=siluf(v);
      else if(epi==2) v=sigf(v+bias[cb+j]);
      Cc[(size_t)(rb2+i)*D+cb+j]=v;
    }
}

// batched: C[M,512] = A[M,K] @ B[K,512] ; tile 64x128
__global__ void __launch_bounds__(256,2) gemm_nn(
    const float* __restrict__ A, const float* __restrict__ Bw, float* __restrict__ Cc,
    int K, long Astride, long Bstride, long Cstride)
{
  __shared__ float As[BK][BM], Bs[BK][BN2];
  GEMM_VARS
  ull accp[2][8]={};
  const float* Ab=A +(size_t)blockIdx.z*Astride+(size_t)blockIdx.y*BM*K;
  const float* Bb=Bw+(size_t)blockIdx.z*Bstride+(size_t)blockIdx.x*BN2;
  float*       Cb=Cc+(size_t)blockIdx.z*Cstride;
  float4 ra =*(const float4*)(Ab+(size_t)lr*K+lk);
  float4 rb0=*(const float4*)(Bb+(size_t)kr*D+nc);
  float4 rb1=*(const float4*)(Bb+(size_t)kr*D+nc+64);
  const int KT=K/BK;
  for(int kt=0;kt<KT;kt++){
    STS_A4(ra)
    { Bs[kr][nc]=rb0.x; Bs[kr][nc+1]=rb0.y; Bs[kr][nc+2]=rb0.z; Bs[kr][nc+3]=rb0.w;
      Bs[kr][nc+64]=rb1.x; Bs[kr][nc+65]=rb1.y; Bs[kr][nc+66]=rb1.z; Bs[kr][nc+67]=rb1.w; }
    __syncthreads();
    if(kt+1<KT){
      int k0=(kt+1)*BK;
      ra =*(const float4*)(Ab+(size_t)lr*K+k0+lk);
      rb0=*(const float4*)(Bb+(size_t)(k0+kr)*D+nc);
      rb1=*(const float4*)(Bb+(size_t)(k0+kr)*D+nc+64);
    }
    FMA_TILE8
    __syncthreads();
  }
  GEMM_UNPACK8
  int rb2=blockIdx.y*BM+(ty<<2), cb=blockIdx.x*BN2+(tx<<3);
  #pragma unroll
  for(int i=0;i<4;i++)
    #pragma unroll
    for(int j=0;j<8;j++)
      Cb[(size_t)(rb2+i)*D+cb+j]=acc[i][j];
}

// ---------------- persistent scan: 64 steps, 5 grid barriers/step (R11, unchanged) ----------------
__global__ void __launch_bounds__(256,2) scan_persist(){
  __shared__ float As[BK][BM], Bs[BK][BN];
  GEMM_VARS
  const int bid=blockIdx.x; const int nb=gridDim.x;

  for(int t=0;t<NCH;t++){
    const int cur=t&1, nxt=cur^1;
    const float al=g_gates[t], th=g_gates[NCH+t], et=g_gates[2*NCH+t];

    // ===== P1: hp[s] = partial of [k;q]@W0^T (256 tasks, split-K=4, 8 k-tiles) =====
    for(int task=bid; task<256; task+=nb){
      int tile=task>>2, s=task&3, by=tile>>3, bx=tile&7;
      ull accp[2][4]={};
      const float* src=(by<4)?g_k:g_q;
      const float* Ab=src+((size_t)(by&3)*SLEN+(size_t)t*CHK)*D+(s<<7);
      const float* Bb=g_W0+(size_t)bx*BN*D+(s<<7);
      float4 ra=*(const float4*)(Ab+(size_t)lr*D+lk);
      float4 rb=*(const float4*)(Bb+(size_t)lr*D+lk);
      for(int kt=0;kt<8;kt++){
        STS_A4(ra) STS_B4(rb)
        __syncthreads();
        if(kt<7){
          int k0=(kt+1)*BK;
          ra=*(const float4*)(Ab+(size_t)lr*D+k0+lk);
          rb=*(const float4*)(Bb+(size_t)lr*D+k0+lk);
        }
        FMA_TILE
        __syncthreads();
      }
      GEMM_UNPACK
      float* Hp=g_hp[s];
      int rw=by*BM+(ty<<2), cb=bx*BN+(tx<<2);
      #pragma unroll
      for(int i=0;i<4;i++)
        #pragma unroll
        for(int j=0;j<4;j++)
          Hp[(size_t)(rw+i)*D+cb+j]=acc[i][j];
    }
    gsync();

    // ===== P2: yp[s] = partial of silu(sum hp)@W1cur^T (256 tasks); bx==0 stores a0 to g_t =====
    for(int task=bid; task<256; task+=nb){
      int tile=task>>2, s=task&3, by=tile>>3, bx=tile&7;
      ull accp[2][4]={};
      size_t aoff=(size_t)(by*BM+lr)*D+(s<<7)+lk;
      const float* Bb=g_W1d[cur]+(size_t)bx*BN*D+(s<<7);
      const bool wA=(bx==0);
      float4 u0,u1,u2,u3,rb,sa;
      u0=*(const float4*)(g_hp[0]+aoff); u1=*(const float4*)(g_hp[1]+aoff);
      u2=*(const float4*)(g_hp[2]+aoff); u3=*(const float4*)(g_hp[3]+aoff);
      rb=*(const float4*)(Bb+(size_t)lr*D+lk);
      sa.x=siluf(u0.x+u1.x+u2.x+u3.x); sa.y=siluf(u0.y+u1.y+u2.y+u3.y);
      sa.z=siluf(u0.z+u1.z+u2.z+u3.z); sa.w=siluf(u0.w+u1.w+u2.w+u3.w);
      for(int kt=0;kt<8;kt++){
        STS_A4(sa) STS_B4(rb)
        if(wA) *(float4*)(g_t+aoff+(size_t)(kt*BK))=sa;
        __syncthreads();
        if(kt<7){
          int k0=(kt+1)*BK;
          u0=*(const float4*)(g_hp[0]+aoff+k0); u1=*(const float4*)(g_hp[1]+aoff+k0);
          u2=*(const float4*)(g_hp[2]+aoff+k0); u3=*(const float4*)(g_hp[3]+aoff+k0);
          rb=*(const float4*)(Bb+(size_t)lr*D+k0+lk);
        }
        FMA_TILE
        __syncthreads();
        if(kt<7){
          sa.x=siluf(u0.x+u1.x+u2.x+u3.x); sa.y=siluf(u0.y+u1.y+u2.y+u3.y);
          sa.z=siluf(u0.z+u1.z+u2.z+u3.z); sa.w=siluf(u0.w+u1.w+u2.w+u3.w);
        }
      }
      GEMM_UNPACK
      float* Yp=g_yp[s];
      int rw=by*BM+(ty<<2), cb=bx*BN+(tx<<2);
      #pragma unroll
      for(int i=0;i<4;i++)
        #pragma unroll
        for(int j=0;j<4;j++)
          Yp[(size_t)(rw+i)*D+cb+j]=acc[i][j];
    }
    gsync();

    // ===== P3: dap (128) + g1p (128) + retrieve (40) =====
    if(bid<128){
      // dap[s] = partial of dy @ W1cur (split-K=4)
      int tile=bid>>2, s=bid&3, by=tile>>3, bx=tile&7;   // by 0..3
      ull accp[2][4]={};
      int row=by*BM+lr; int bb=row>>6, cc=row&63;
      size_t aoff=(size_t)row*D+(s<<7)+lk;
      const float* vb=g_v+((size_t)bb*SLEN+(size_t)t*CHK+cc)*D+(s<<7)+lk;
      const float* W1c=g_W1d[cur];
      float4 y0,y1,y2,y3,vv,rb,sa;
      y0=*(const float4*)(g_yp[0]+aoff); y1=*(const float4*)(g_yp[1]+aoff);
      y2=*(const float4*)(g_yp[2]+aoff); y3=*(const float4*)(g_yp[3]+aoff);
      vv=*(const float4*)vb;
      rb=*(const float4*)(W1c+(size_t)((s<<7)+kr)*D+(size_t)bx*BN+nc);
      sa.x=GSCALE*(y0.x+y1.x+y2.x+y3.x-vv.x); sa.y=GSCALE*(y0.y+y1.y+y2.y+y3.y-vv.y);
      sa.z=GSCALE*(y0.z+y1.z+y2.z+y3.z-vv.z); sa.w=GSCALE*(y0.w+y1.w+y2.w+y3.w-vv.w);
      for(int kt=0;kt<8;kt++){
        STS_A4(sa) STS_BT4(rb)
        __syncthreads();
        if(kt<7){
          int k0=(kt+1)*BK;
          y0=*(const float4*)(g_yp[0]+aoff+k0); y1=*(const float4*)(g_yp[1]+aoff+k0);
          y2=*(const float4*)(g_yp[2]+aoff+k0); y3=*(const float4*)(g_yp[3]+aoff+k0);
          vv=*(const float4*)(vb+k0);
          rb=*(const float4*)(W1c+(size_t)((s<<7)+k0+kr)*D+(size_t)bx*BN+nc);
        }
        FMA_TILE
        __syncthreads();
        if(kt<7){
          sa.x=GSCALE*(y0.x+y1.x+y2.x+y3.x-vv.x); sa.y=GSCALE*(y0.y+y1.y+y2.y+y3.y-vv.y);
          sa.z=GSCALE*(y0.z+y1.z+y2.z+y3.z-vv.z); sa.w=GSCALE*(y0.w+y1.w+y2.w+y3.w-vv.w);
        }
      }
      GEMM_UNPACK
      float* Dp=g_dap[s];
      int rw=by*BM+(ty<<2), cb=bx*BN+(tx<<2);
      #pragma unroll
      for(int i=0;i<4;i++)
        #pragma unroll
        for(int j=0;j<4;j++)
          Dp[(size_t)(rw+i)*D+cb+j]=acc[i][j];
    } else if(bid<256){
      // g1p[s] = partial of gW1 = dy^T @ a0 (a0 from g_t), split-K=2
      int idx=bid-128; int tile=idx>>1, s=idx&1, by=tile>>3, bx=tile&7;
      ull accp[2][4]={};
      float4 y0,y1,y2,y3,vv,rb,sa;
      {
        int r=(s<<7)+kr; int bb=r>>6, cc=r&63;
        size_t yoff=(size_t)r*D+(size_t)by*BM+nc;
        y0=*(const float4*)(g_yp[0]+yoff); y1=*(const float4*)(g_yp[1]+yoff);
        y2=*(const float4*)(g_yp[2]+yoff); y3=*(const float4*)(g_yp[3]+yoff);
        vv=*(const float4*)(g_v+((size_t)bb*SLEN+(size_t)t*CHK+cc)*D+(size_t)by*BM+nc);
        rb=*(const float4*)(g_t+(size_t)r*D+(size_t)bx*BN+nc);
      }
      sa.x=GSCALE*(y0.x+y1.x+y2.x+y3.x-vv.x); sa.y=GSCALE*(y0.y+y1.y+y2.y+y3.y-vv.y);
      sa.z=GSCALE*(y0.z+y1.z+y2.z+y3.z-vv.z); sa.w=GSCALE*(y0.w+y1.w+y2.w+y3.w-vv.w);
      for(int kt=0;kt<8;kt++){
        STS_AT4(sa) STS_BT4(rb)
        __syncthreads();
        if(kt<7){
          int r=(s<<7)+(kt+1)*BK+kr; int bb=r>>6, cc=r&63;
          size_t yoff=(size_t)r*D+(size_t)by*BM+nc;
          y0=*(const float4*)(g_yp[0]+yoff); y1=*(const float4*)(g_yp[1]+yoff);
          y2=*(const float4*)(g_yp[2]+yoff); y3=*(const float4*)(g_yp[3]+yoff);
          vv=*(const float4*)(g_v+((size_t)bb*SLEN+(size_t)t*CHK+cc)*D+(size_t)by*BM+nc);
          rb=*(const float4*)(g_t+(size_t)r*D+(size_t)bx*BN+nc);
        }
        FMA_TILE
        __syncthreads();
        if(kt<7){
          sa.x=GSCALE*(y0.x+y1.x+y2.x+y3.x-vv.x); sa.y=GSCALE*(y0.y+y1.y+y2.y+y3.y-vv.y);
          sa.z=GSCALE*(y0.z+y1.z+y2.z+y3.z-vv.z); sa.w=GSCALE*(y0.w+y1.w+y2.w+y3.w-vv.w);
        }
      }
      GEMM_UNPACK
      float* Gp=g_g1p[s];
      int eb=by*BM+(ty<<2), db=bx*BN+(tx<<2);
      #pragma unroll
      for(int i=0;i<4;i++)
        #pragma unroll
        for(int j=0;j<4;j++)
          Gp[(size_t)(eb+i)*D+db+j]=acc[i][j];
    } else {
      for(int idx=(bid-256)*256+tid; idx<SCANR*D; idx+=(GRID_P-256)*256){
        int r=idx>>9, c=idx&511;
        size_t off=(size_t)(SCANR+r)*D+c;
        float val=g_yp[0][off]+g_yp[1][off]+g_yp[2][off]+g_yp[3][off];
        int bb=r>>6, cc=r&63;
        g_r[((size_t)bb*SLEN+(size_t)t*CHK+cc)*D+c]=val;
      }
    }
    gsync();

    // ===== P4: g0p (128, dh recomputed) + W1 update (128) =====
    if(bid<128){
      int tile=bid>>1, s=bid&1, by=tile>>3, bx=tile&7;
      ull accp[2][4]={};
      float4 d0,d1,d2,d3,u0,u1,u2,u3,rb,sa;
      {
        int r=(s<<7)+kr; int bb=r>>6, cc=r&63;
        size_t off=(size_t)r*D+(size_t)by*BM+nc;
        d0=*(const float4*)(g_dap[0]+off); d1=*(const float4*)(g_dap[1]+off);
        d2=*(const float4*)(g_dap[2]+off); d3=*(const float4*)(g_dap[3]+off);
        u0=*(const float4*)(g_hp[0]+off);  u1=*(const float4*)(g_hp[1]+off);
        u2=*(const float4*)(g_hp[2]+off);  u3=*(const float4*)(g_hp[3]+off);
        rb=*(const float4*)(g_k+((size_t)bb*SLEN+(size_t)t*CHK+cc)*D+(size_t)bx*BN+nc);
      }
      sa.x=(d0.x+d1.x+d2.x+d3.x)*silupf(u0.x+u1.x+u2.x+u3.x);
      sa.y=(d0.y+d1.y+d2.y+d3.y)*silupf(u0.y+u1.y+u2.y+u3.y);
      sa.z=(d0.z+d1.z+d2.z+d3.z)*silupf(u0.z+u1.z+u2.z+u3.z);
      sa.w=(d0.w+d1.w+d2.w+d3.w)*silupf(u0.w+u1.w+u2.w+u3.w);
      for(int kt=0;kt<8;kt++){
        STS_AT4(sa) STS_BT4(rb)
        __syncthreads();
        if(kt<7){
          int r=(s<<7)+(kt+1)*BK+kr; int bb=r>>6, cc=r&63;
          size_t off=(size_t)r*D+(size_t)by*BM+nc;
          d0=*(const float4*)(g_dap[0]+off); d1=*(const float4*)(g_dap[1]+off);
          d2=*(const float4*)(g_dap[2]+off); d3=*(const float4*)(g_dap[3]+off);
          u0=*(const float4*)(g_hp[0]+off);  u1=*(const float4*)(g_hp[1]+off);
          u2=*(const float4*)(g_hp[2]+off);  u3=*(const float4*)(g_hp[3]+off);
          rb=*(const float4*)(g_k+((size_t)bb*SLEN+(size_t)t*CHK+cc)*D+(size_t)bx*BN+nc);
        }
        FMA_TILE
        __syncthreads();
        if(kt<7){
          sa.x=(d0.x+d1.x+d2.x+d3.x)*silupf(u0.x+u1.x+u2.x+u3.x);
          sa.y=(d0.y+d1.y+d2.y+d3.y)*silupf(u0.y+u1.y+u2.y+u3.y);
          sa.z=(d0.z+d1.z+d2.z+d3.z)*silupf(u0.z+u1.z+u2.z+u3.z);
          sa.w=(d0.w+d1.w+d2.w+d3.w)*silupf(u0.w+u1.w+u2.w+u3.w);
        }
      }
      GEMM_UNPACK
      float* Gp=g_g0p[s];
      int eb=by*BM+(ty<<2), db=bx*BN+(tx<<2);
      #pragma unroll
      for(int i=0;i<4;i++)
        #pragma unroll
        for(int j=0;j<4;j++)
          Gp[(size_t)(eb+i)*D+db+j]=acc[i][j];
    } else if(bid<256){
      const float* W1c=g_W1d[cur]; float* W1n=g_W1d[nxt];
      for(int i4=(bid-128)*256+tid; i4<D*D/4; i4+=128*256){
        float4 m=*(((float4*)g_m1)+i4);
        float4 ga=*(((const float4*)g_g1p[0])+i4);
        float4 gb=*(((const float4*)g_g1p[1])+i4);
        float4 w=*(((const float4*)W1c)+i4);
        m.x=et*m.x-th*(ga.x+gb.x); m.y=et*m.y-th*(ga.y+gb.y);
        m.z=et*m.z-th*(ga.z+gb.z); m.w=et*m.w-th*(ga.w+gb.w);
        float4 wn; wn.x=(1.0f-al)*w.x+m.x; wn.y=(1.0f-al)*w.y+m.y;
        wn.z=(1.0f-al)*w.z+m.z; wn.w=(1.0f-al)*w.w+m.w;
        *(((float4*)g_m1)+i4)=m;
        *(((float4*)W1n)+i4)=wn;
      }
    }
    gsync();

    // ===== P5: W0 update =====
    for(int i4=bid*256+tid; i4<D*D/4; i4+=GRID_P*256){
      float4 m=*(((float4*)g_m0)+i4);
      float4 ga=*(((const float4*)g_g0p[0])+i4);
      float4 gb=*(((const float4*)g_g0p[1])+i4);
      float4 w=*(((float4*)g_W0)+i4);
      m.x=et*m.x-th*(ga.x+gb.x); m.y=et*m.y-th*(ga.y+gb.y);
      m.z=et*m.z-th*(ga.z+gb.z); m.w=et*m.w-th*(ga.w+gb.w);
      w.x=(1.0f-al)*w.x+m.x; w.y=(1.0f-al)*w.y+m.y;
      w.z=(1.0f-al)*w.z+m.z; w.w=(1.0f-al)*w.w+m.w;
      *(((float4*)g_m0)+i4)=m;
      *(((float4*)g_W0)+i4)=w;
    }
    gsync();
  }
}

// ---------------- launch ----------------
extern "C" void kernel_launch(void* const* d_in, const int* in_sizes, int n_in,
                              void* d_out, int out_size)
{
    const float* x    = (const float*)d_in[0];
    const float* Mm   = (const float*)d_in[1];
    const float* memW = (const float*)d_in[2];
    const float* Wk   = (const float*)d_in[3];
    const float* Wv   = (const float*)d_in[4];
    const float* Wq   = (const float*)d_in[5];
    const float* Wout = (const float*)d_in[6];
    const float* Wgd  = (const float*)d_in[7];
    const float* bgd  = (const float*)d_in[8];
    const float* Wgl  = (const float*)d_in[9];
    const float* bgl  = (const float*)d_in[10];
    const float* Wgm  = (const float*)d_in[11];
    const float* bgm  = (const float*)d_in[12];
    const float* gs   = (const float*)d_in[13];
    const float* gr   = (const float*)d_in[14];
    float* outp = (float*)d_out;

    float *p_xs,*p_t,*p_k,*p_v,*p_q,*p_r,*p_cm,*p_gtmp;
    cudaGetSymbolAddress((void**)&p_xs,  g_xs);
    cudaGetSymbolAddress((void**)&p_t,   g_t);
    cudaGetSymbolAddress((void**)&p_k,   g_k);
    cudaGetSymbolAddress((void**)&p_v,   g_v);
    cudaGetSymbolAddress((void**)&p_q,   g_q);
    cudaGetSymbolAddress((void**)&p_r,   g_r);
    cudaGetSymbolAddress((void**)&p_cm,  g_cm);
    cudaGetSymbolAddress((void**)&p_gtmp,g_gtmp);

    // gates
    chunk_mean_k<<<BATCH*NCH, D>>>(x);
    gemm_nt<<<dim3(4,4),256>>>(p_cm, Wgd, bgd, p_gtmp,                 D, 2);
    gemm_nt<<<dim3(4,4),256>>>(p_cm, Wgl, bgl, p_gtmp +   BATCH*NCH*D, D, 2);
    gemm_nt<<<dim3(4,4),256>>>(p_cm, Wgm, bgm, p_gtmp + 2*BATCH*NCH*D, D, 2);
    gate_reduce_k<<<dim3(NCH,3),256>>>();

    // norms + projections
    rmsnorm_k<<<NTOK,256>>>(x, gs, p_xs);
    rmsnorm_k<<<NTOK,256>>>(x, gr, p_t);
    gemm_nt<<<dim3(4,NTOK/BM),256>>>(p_t, Wq, 0, p_q, D, 1);
    l2norm_k<<<NTOK,256>>>(p_q);
    gemm_nn<<<dim3(4,SLEN/BM,BATCH),256>>>(p_xs, Mm, p_t, D,
        (long)SLEN*D, (long)D*D, (long)SLEN*D);
    gemm_nt<<<dim3(4,NTOK/BM),256>>>(p_t, Wk, 0, p_k, D, 1);
    l2norm_k<<<NTOK,256>>>(p_k);
    gemm_nt<<<dim3(4,NTOK/BM),256>>>(p_xs, Wv, 0, p_v, D, 1);

    // init fast weights + momentum
    init_w_k<<<(D*D)/256,256>>>(memW);

    // fused scan
    scan_persist<<<GRID_P,256>>>();

    // final projection
    gemm_nt<<<dim3(4,NTOK/BM),256>>>(p_r, Wout, 0, outp, D, 0);
}

// round 17
// speedup vs baseline: 1.1574x; 1.1574x over previous
#include <cuda_runtime.h>
#include <math.h>

#define D     512
#define SLEN  4096
#define BATCH 4
#define CHK   64
#define NCH   64
#define NTOK  (BATCH*SLEN)
#define SCANR 256
#define BM 64
#define BN 64
#define BK 16
#define GRID_P 296

#define GSCALE   (2.0f/131072.0f)
#define DECAY    0.01f
#define LRATE    0.1f
#define MOMC     0.9f
#define EPS_RMS  1.1920929e-07f
#define EPS_L2   1e-12f

typedef unsigned long long ull;

// ---------------- scratch ----------------
__device__ float g_xs[NTOK*D];
__device__ float g_t [NTOK*D];       // prep temp; in scan reused as a0=silu(sum hp)
__device__ float g_k [NTOK*D];
__device__ float g_v [NTOK*D];
__device__ float g_q [NTOK*D];
__device__ float g_r [NTOK*D];
__device__ float g_cm[BATCH*NCH*D];
__device__ float g_gtmp[3*BATCH*NCH*D];
__device__ float g_gates[3*NCH];
__device__ float g_W0[D*D], g_m0[D*D], g_m1[D*D];
__device__ float g_W1d[2][D*D];      // double-buffered W1
__device__ float g_hp[4][D*D];       // split-K=4 partials of [k;q]@W0^T (512 rows)
__device__ float g_yp[4][D*D];       // split-K=4 partials of [a0;aq]@W1^T
__device__ float g_dap[4][SCANR*D];  // split-K=4 partials of dy@W1
__device__ float g_g1p[2][D*D];      // split-K=2 partials of gW1
__device__ float g_g0p[2][D*D];      // split-K=2 partials of gW0
__device__ unsigned g_barc = 0;
__device__ volatile unsigned g_barp = 0;

// ---------------- helpers ----------------
__device__ __forceinline__ float siluf(float v)  { return v/(1.0f+expf(-v)); }
__device__ __forceinline__ float sigf(float v)   { return 1.0f/(1.0f+expf(-v)); }
__device__ __forceinline__ float silupf(float v) { float s=1.0f/(1.0f+expf(-v)); return s*(1.0f+v*(1.0f-s)); }
__device__ __forceinline__ ull dup2(float x){ ull r; asm("mov.b64 %0,{%1,%1};":"=l"(r):"f"(x)); return r; }
__device__ __forceinline__ void fma2(ull &c, ull a, ull b){
  asm("fma.rn.f32x2 %0,%1,%2,%0;" : "+l"(c) : "l"(a), "l"(b));
}

__device__ __forceinline__ float blockReduce256(float v, float* red){
  int tid=threadIdx.x; red[tid]=v; __syncthreads();
  #pragma unroll
  for(int o=128;o>0;o>>=1){ if(tid<o) red[tid]+=red[tid+o]; __syncthreads(); }
  return red[0];
}

// grid-wide sense barrier (atomic counter; proven fastest in R11 vs flag design)
__device__ __forceinline__ void gsync(){
  __threadfence();
  __syncthreads();
  if(threadIdx.x==0){
    unsigned ph=g_barp;
    if(atomicAdd(&g_barc,1u)==gridDim.x-1u){
      g_barc=0; __threadfence(); g_barp=ph+1u;
    } else {
      while(g_barp==ph){ __nanosleep(32); }
    }
  }
  __syncthreads();
}

// ---------------- small kernels ----------------
__global__ void chunk_mean_k(const float* __restrict__ x){
  int rc=blockIdx.x; int b=rc>>6, t=rc&63; int d=threadIdx.x;
  const float* p=x+((size_t)b*SLEN+(size_t)t*CHK)*D+d;
  float s=0.f;
  #pragma unroll 8
  for(int c=0;c<CHK;c++) s+=p[(size_t)c*D];
  g_cm[(size_t)rc*D+d]=s*(1.0f/CHK);
}

__global__ void gate_reduce_k(){
  __shared__ float red[256];
  int t=blockIdx.x, g=blockIdx.y, tid=threadIdx.x;
  float s=0.f;
  for(int i=tid;i<BATCH*D;i+=256){
    int b=i>>9, e=i&511;
    s+=g_gtmp[((size_t)g*BATCH*NCH+(size_t)b*NCH+t)*D+e];
  }
  float tot=blockReduce256(s,red);
  if(tid==0){
    float sc=(g==0)?DECAY:((g==1)?LRATE:MOMC);
    g_gates[g*NCH+t]=sc*tot/(float)(BATCH*D);
  }
}

__global__ void rmsnorm_k(const float* __restrict__ x, const float* __restrict__ g,
                          float* __restrict__ outp){
  __shared__ float red[256];
  size_t base=(size_t)blockIdx.x*D; int tid=threadIdx.x;
  float v0=x[base+tid], v1=x[base+tid+256];
  float tot=blockReduce256(v0*v0+v1*v1,red);
  float r=rsqrtf(tot*(1.0f/D)+EPS_RMS);
  outp[base+tid]=v0*r*g[tid];
  outp[base+tid+256]=v1*r*g[tid+256];
}

__global__ void l2norm_k(float* __restrict__ p){
  __shared__ float red[256];
  size_t base=(size_t)blockIdx.x*D; int tid=threadIdx.x;
  float v0=p[base+tid], v1=p[base+tid+256];
  float tot=blockReduce256(v0*v0+v1*v1,red);
  float inv=1.0f/fmaxf(sqrtf(tot),EPS_L2);
  p[base+tid]=v0*inv; p[base+tid+256]=v1*inv;
}

__global__ void init_w_k(const float* __restrict__ memW){
  int i=blockIdx.x*256+threadIdx.x;
  g_W0[i]=memW[i]; g_W1d[0][i]=memW[D*D+i]; g_m0[i]=0.f; g_m1[i]=0.f;
}

// ---------------- GEMM core (broadcast A: warp=8-row slab, lane=col pair) ----------------
// Per kk per warp: A = 4x LDS.64 broadcast (~free), B = LDS.64 sweep (conflict-free).
// 0.56 B/MAC -> FMA-bound. Summation order per output element identical to 4x4 core.
#define GEMM_VARS \
  const int tid=threadIdx.x; \
  const int wrp=tid>>5, cp=tid&31; \
  const int lr=tid>>2, lk=(tid&3)<<2; \
  const int kr=tid>>4, nc=(tid&15)<<2; \
  (void)lr;(void)lk;(void)kr;(void)nc;(void)wrp;(void)cp;

#define FMA_TILE \
  _Pragma("unroll") \
  for(int kk=0;kk<BK;kk++){ \
    const float* ap=&As[kk][wrp<<3]; \
    ull a01=*(const ull*)(ap),   a23=*(const ull*)(ap+2); \
    ull a45=*(const ull*)(ap+4), a67=*(const ull*)(ap+6); \
    float2 bp=*(const float2*)&Bs[kk][cp<<1]; \
    ull b0=dup2(bp.x), b1=dup2(bp.y); \
    fma2(accp[0][0],a01,b0); fma2(accp[0][1],a01,b1); \
    fma2(accp[1][0],a23,b0); fma2(accp[1][1],a23,b1); \
    fma2(accp[2][0],a45,b0); fma2(accp[2][1],a45,b1); \
    fma2(accp[3][0],a67,b0); fma2(accp[3][1],a67,b1); \
  }

#define GEMM_UNPACK \
  float acc[8][2]; \
  _Pragma("unroll") \
  for(int p=0;p<4;p++){ \
    asm("mov.b64 {%0,%1},%2;":"=f"(acc[2*p][0]),"=f"(acc[2*p+1][0]):"l"(accp[p][0])); \
    asm("mov.b64 {%0,%1},%2;":"=f"(acc[2*p][1]),"=f"(acc[2*p+1][1]):"l"(accp[p][1])); \
  }

#define STS_A4(r4) { As[lk][lr]=r4.x; As[lk+1][lr]=r4.y; As[lk+2][lr]=r4.z; As[lk+3][lr]=r4.w; }
#define STS_B4(r4) { Bs[lk][lr]=r4.x; Bs[lk+1][lr]=r4.y; Bs[lk+2][lr]=r4.z; Bs[lk+3][lr]=r4.w; }
#define STS_AT4(r4){ As[kr][nc]=r4.x; As[kr][nc+1]=r4.y; As[kr][nc+2]=r4.z; As[kr][nc+3]=r4.w; }
#define STS_BT4(r4){ Bs[kr][nc]=r4.x; Bs[kr][nc+1]=r4.y; Bs[kr][nc+2]=r4.z; Bs[kr][nc+3]=r4.w; }

// store 8x2 accumulator block at (rowbase, colbase) into row-major [.][D] array
#define EPI_STORE(DST, rowbase, colbase) { \
  int rw=(rowbase)+(wrp<<3), cb=(colbase)+(cp<<1); \
  _Pragma("unroll") \
  for(int i=0;i<8;i++){ \
    float2 st; st.x=acc[i][0]; st.y=acc[i][1]; \
    *(float2*)&(DST)[(size_t)(rw+i)*D+cb]=st; \
  } \
}

// ---------------- generic GEMMs (prep + final), prefetched ----------------
__global__ void __launch_bounds__(256) gemm_nt(
    const float* __restrict__ A, const float* __restrict__ Bw,
    const float* __restrict__ bias, float* __restrict__ Cc, int K, int epi)
{
  __shared__ float As[BK][BM], Bs[BK][BN];
  GEMM_VARS
  ull accp[4][2]={};
  const float* Ab=A +(size_t)blockIdx.y*BM*K;
  const float* Bb=Bw+(size_t)blockIdx.x*BN*K;
  float4 ra=*(const float4*)(Ab+(size_t)lr*K+lk);
  float4 rb=*(const float4*)(Bb+(size_t)lr*K+lk);
  const int KT=K/BK;
  for(int kt=0;kt<KT;kt++){
    STS_A4(ra) STS_B4(rb)
    __syncthreads();
    if(kt+1<KT){
      int k0=(kt+1)*BK;
      ra=*(const float4*)(Ab+(size_t)lr*K+k0+lk);
      rb=*(const float4*)(Bb+(size_t)lr*K+k0+lk);
    }
    FMA_TILE
    __syncthreads();
  }
  GEMM_UNPACK
  {
    int rw=blockIdx.y*BM+(wrp<<3), cb=blockIdx.x*BN+(cp<<1);
    #pragma unroll
    for(int i=0;i<8;i++){
      float w0=acc[i][0], w1=acc[i][1];
      if(epi==1){ w0=siluf(w0); w1=siluf(w1); }
      else if(epi==2){ w0=sigf(w0+bias[cb]); w1=sigf(w1+bias[cb+1]); }
      float2 st; st.x=w0; st.y=w1;
      *(float2*)&Cc[(size_t)(rw+i)*D+cb]=st;
    }
  }
}

__global__ void __launch_bounds__(256) gemm_nn(
    const float* __restrict__ A, const float* __restrict__ Bw, float* __restrict__ Cc,
    int K, long Astride, long Bstride, long Cstride)
{
  __shared__ float As[BK][BM], Bs[BK][BN];
  GEMM_VARS
  ull accp[4][2]={};
  const float* Ab=A +(size_t)blockIdx.z*Astride+(size_t)blockIdx.y*BM*K;
  const float* Bb=Bw+(size_t)blockIdx.z*Bstride+(size_t)blockIdx.x*BN;
  float*       Cb=Cc+(size_t)blockIdx.z*Cstride;
  float4 ra=*(const float4*)(Ab+(size_t)lr*K+lk);
  float4 rb=*(const float4*)(Bb+(size_t)kr*D+nc);
  const int KT=K/BK;
  for(int kt=0;kt<KT;kt++){
    STS_A4(ra) STS_BT4(rb)
    __syncthreads();
    if(kt+1<KT){
      int k0=(kt+1)*BK;
      ra=*(const float4*)(Ab+(size_t)lr*K+k0+lk);
      rb=*(const float4*)(Bb+(size_t)(k0+kr)*D+nc);
    }
    FMA_TILE
    __syncthreads();
  }
  GEMM_UNPACK
  EPI_STORE(Cb, blockIdx.y*BM, blockIdx.x*BN)
}

// ---------------- persistent scan: 64 steps, 5 grid barriers/step ----------------
__global__ void __launch_bounds__(256,2) scan_persist(){
  __shared__ float As[BK][BM], Bs[BK][BN];
  GEMM_VARS
  const int bid=blockIdx.x; const int nb=gridDim.x;

  for(int t=0;t<NCH;t++){
    const int cur=t&1, nxt=cur^1;
    const float al=g_gates[t], th=g_gates[NCH+t], et=g_gates[2*NCH+t];

    // ===== P1: hp[s] = partial of [k;q]@W0^T (256 tasks, split-K=4, 8 k-tiles) =====
    for(int task=bid; task<256; task+=nb){
      int tile=task>>2, s=task&3, by=tile>>3, bx=tile&7;
      ull accp[4][2]={};
      const float* src=(by<4)?g_k:g_q;
      const float* Ab=src+((size_t)(by&3)*SLEN+(size_t)t*CHK)*D+(s<<7);
      const float* Bb=g_W0+(size_t)bx*BN*D+(s<<7);
      float4 ra=*(const float4*)(Ab+(size_t)lr*D+lk);
      float4 rb=*(const float4*)(Bb+(size_t)lr*D+lk);
      for(int kt=0;kt<8;kt++){
        STS_A4(ra) STS_B4(rb)
        __syncthreads();
        if(kt<7){
          int k0=(kt+1)*BK;
          ra=*(const float4*)(Ab+(size_t)lr*D+k0+lk);
          rb=*(const float4*)(Bb+(size_t)lr*D+k0+lk);
        }
        FMA_TILE
        __syncthreads();
      }
      GEMM_UNPACK
      EPI_STORE(g_hp[s], by*BM, bx*BN)
    }
    gsync();

    // ===== P2: yp[s] = partial of silu(sum hp)@W1cur^T (256 tasks); bx==0 stores a0 to g_t =====
    for(int task=bid; task<256; task+=nb){
      int tile=task>>2, s=task&3, by=tile>>3, bx=tile&7;
      ull accp[4][2]={};
      size_t aoff=(size_t)(by*BM+lr)*D+(s<<7)+lk;
      const float* Bb=g_W1d[cur]+(size_t)bx*BN*D+(s<<7);
      const bool wA=(bx==0);
      float4 u0,u1,u2,u3,rb,sa;
      u0=*(const float4*)(g_hp[0]+aoff); u1=*(const float4*)(g_hp[1]+aoff);
      u2=*(const float4*)(g_hp[2]+aoff); u3=*(const float4*)(g_hp[3]+aoff);
      rb=*(const float4*)(Bb+(size_t)lr*D+lk);
      sa.x=siluf(u0.x+u1.x+u2.x+u3.x); sa.y=siluf(u0.y+u1.y+u2.y+u3.y);
      sa.z=siluf(u0.z+u1.z+u2.z+u3.z); sa.w=siluf(u0.w+u1.w+u2.w+u3.w);
      for(int kt=0;kt<8;kt++){
        STS_A4(sa) STS_B4(rb)
        if(wA) *(float4*)(g_t+aoff+(size_t)(kt*BK))=sa;
        __syncthreads();
        if(kt<7){
          int k0=(kt+1)*BK;
          u0=*(const float4*)(g_hp[0]+aoff+k0); u1=*(const float4*)(g_hp[1]+aoff+k0);
          u2=*(const float4*)(g_hp[2]+aoff+k0); u3=*(const float4*)(g_hp[3]+aoff+k0);
          rb=*(const float4*)(Bb+(size_t)lr*D+k0+lk);
        }
        FMA_TILE
        __syncthreads();
        if(kt<7){
          sa.x=siluf(u0.x+u1.x+u2.x+u3.x); sa.y=siluf(u0.y+u1.y+u2.y+u3.y);
          sa.z=siluf(u0.z+u1.z+u2.z+u3.z); sa.w=siluf(u0.w+u1.w+u2.w+u3.w);
        }
      }
      GEMM_UNPACK
      EPI_STORE(g_yp[s], by*BM, bx*BN)
    }
    gsync();

    // ===== P3: dap (128) + g1p (128) + retrieve (40) =====
    if(bid<128){
      // dap[s] = partial of dy @ W1cur (split-K=4)
      int tile=bid>>2, s=bid&3, by=tile>>3, bx=tile&7;   // by 0..3
      ull accp[4][2]={};
      int row=by*BM+lr; int bb=row>>6, cc=row&63;
      size_t aoff=(size_t)row*D+(s<<7)+lk;
      const float* vb=g_v+((size_t)bb*SLEN+(size_t)t*CHK+cc)*D+(s<<7)+lk;
      const float* W1c=g_W1d[cur];
      float4 y0,y1,y2,y3,vv,rb,sa;
      y0=*(const float4*)(g_yp[0]+aoff); y1=*(const float4*)(g_yp[1]+aoff);
      y2=*(const float4*)(g_yp[2]+aoff); y3=*(const float4*)(g_yp[3]+aoff);
      vv=*(const float4*)vb;
      rb=*(const float4*)(W1c+(size_t)((s<<7)+kr)*D+(size_t)bx*BN+nc);
      sa.x=GSCALE*(y0.x+y1.x+y2.x+y3.x-vv.x); sa.y=GSCALE*(y0.y+y1.y+y2.y+y3.y-vv.y);
      sa.z=GSCALE*(y0.z+y1.z+y2.z+y3.z-vv.z); sa.w=GSCALE*(y0.w+y1.w+y2.w+y3.w-vv.w);
      for(int kt=0;kt<8;kt++){
        STS_A4(sa) STS_BT4(rb)
        __syncthreads();
        if(kt<7){
          int k0=(kt+1)*BK;
          y0=*(const float4*)(g_yp[0]+aoff+k0); y1=*(const float4*)(g_yp[1]+aoff+k0);
          y2=*(const float4*)(g_yp[2]+aoff+k0); y3=*(const float4*)(g_yp[3]+aoff+k0);
          vv=*(const float4*)(vb+k0);
          rb=*(const float4*)(W1c+(size_t)((s<<7)+k0+kr)*D+(size_t)bx*BN+nc);
        }
        FMA_TILE
        __syncthreads();
        if(kt<7){
          sa.x=GSCALE*(y0.x+y1.x+y2.x+y3.x-vv.x); sa.y=GSCALE*(y0.y+y1.y+y2.y+y3.y-vv.y);
          sa.z=GSCALE*(y0.z+y1.z+y2.z+y3.z-vv.z); sa.w=GSCALE*(y0.w+y1.w+y2.w+y3.w-vv.w);
        }
      }
      GEMM_UNPACK
      EPI_STORE(g_dap[s], by*BM, bx*BN)
    } else if(bid<256){
      // g1p[s] = partial of gW1 = dy^T @ a0 (a0 from g_t), split-K=2
      int idx=bid-128; int tile=idx>>1, s=idx&1, by=tile>>3, bx=tile&7;
      ull accp[4][2]={};
      float4 y0,y1,y2,y3,vv,rb,sa;
      {
        int r=(s<<7)+kr; int bb=r>>6, cc=r&63;
        size_t yoff=(size_t)r*D+(size_t)by*BM+nc;
        y0=*(const float4*)(g_yp[0]+yoff); y1=*(const float4*)(g_yp[1]+yoff);
        y2=*(const float4*)(g_yp[2]+yoff); y3=*(const float4*)(g_yp[3]+yoff);
        vv=*(const float4*)(g_v+((size_t)bb*SLEN+(size_t)t*CHK+cc)*D+(size_t)by*BM+nc);
        rb=*(const float4*)(g_t+(size_t)r*D+(size_t)bx*BN+nc);
      }
      sa.x=GSCALE*(y0.x+y1.x+y2.x+y3.x-vv.x); sa.y=GSCALE*(y0.y+y1.y+y2.y+y3.y-vv.y);
      sa.z=GSCALE*(y0.z+y1.z+y2.z+y3.z-vv.z); sa.w=GSCALE*(y0.w+y1.w+y2.w+y3.w-vv.w);
      for(int kt=0;kt<8;kt++){
        STS_AT4(sa) STS_BT4(rb)
        __syncthreads();
        if(kt<7){
          int r=(s<<7)+(kt+1)*BK+kr; int bb=r>>6, cc=r&63;
          size_t yoff=(size_t)r*D+(size_t)by*BM+nc;
          y0=*(const float4*)(g_yp[0]+yoff); y1=*(const float4*)(g_yp[1]+yoff);
          y2=*(const float4*)(g_yp[2]+yoff); y3=*(const float4*)(g_yp[3]+yoff);
          vv=*(const float4*)(g_v+((size_t)bb*SLEN+(size_t)t*CHK+cc)*D+(size_t)by*BM+nc);
          rb=*(const float4*)(g_t+(size_t)r*D+(size_t)bx*BN+nc);
        }
        FMA_TILE
        __syncthreads();
        if(kt<7){
          sa.x=GSCALE*(y0.x+y1.x+y2.x+y3.x-vv.x); sa.y=GSCALE*(y0.y+y1.y+y2.y+y3.y-vv.y);
          sa.z=GSCALE*(y0.z+y1.z+y2.z+y3.z-vv.z); sa.w=GSCALE*(y0.w+y1.w+y2.w+y3.w-vv.w);
        }
      }
      GEMM_UNPACK
      EPI_STORE(g_g1p[s], by*BM, bx*BN)
    } else {
      for(int idx=(bid-256)*256+tid; idx<SCANR*D; idx+=(GRID_P-256)*256){
        int r=idx>>9, c=idx&511;
        size_t off=(size_t)(SCANR+r)*D+c;
        float val=g_yp[0][off]+g_yp[1][off]+g_yp[2][off]+g_yp[3][off];
        int bb=r>>6, cc=r&63;
        g_r[((size_t)bb*SLEN+(size_t)t*CHK+cc)*D+c]=val;
      }
    }
    gsync();

    // ===== P4: g0p (128, dh recomputed) + W1 update (128) =====
    if(bid<128){
      int tile=bid>>1, s=bid&1, by=tile>>3, bx=tile&7;
      ull accp[4][2]={};
      float4 d0,d1,d2,d3,u0,u1,u2,u3,rb,sa;
      {
        int r=(s<<7)+kr; int bb=r>>6, cc=r&63;
        size_t off=(size_t)r*D+(size_t)by*BM+nc;
        d0=*(const float4*)(g_dap[0]+off); d1=*(const float4*)(g_dap[1]+off);
        d2=*(const float4*)(g_dap[2]+off); d3=*(const float4*)(g_dap[3]+off);
        u0=*(const float4*)(g_hp[0]+off);  u1=*(const float4*)(g_hp[1]+off);
        u2=*(const float4*)(g_hp[2]+off);  u3=*(const float4*)(g_hp[3]+off);
        rb=*(const float4*)(g_k+((size_t)bb*SLEN+(size_t)t*CHK+cc)*D+(size_t)bx*BN+nc);
      }
      sa.x=(d0.x+d1.x+d2.x+d3.x)*silupf(u0.x+u1.x+u2.x+u3.x);
      sa.y=(d0.y+d1.y+d2.y+d3.y)*silupf(u0.y+u1.y+u2.y+u3.y);
      sa.z=(d0.z+d1.z+d2.z+d3.z)*silupf(u0.z+u1.z+u2.z+u3.z);
      sa.w=(d0.w+d1.w+d2.w+d3.w)*silupf(u0.w+u1.w+u2.w+u3.w);
      for(int kt=0;kt<8;kt++){
        STS_AT4(sa) STS_BT4(rb)
        __syncthreads();
        if(kt<7){
          int r=(s<<7)+(kt+1)*BK+kr; int bb=r>>6, cc=r&63;
          size_t off=(size_t)r*D+(size_t)by*BM+nc;
          d0=*(const float4*)(g_dap[0]+off); d1=*(const float4*)(g_dap[1]+off);
          d2=*(const float4*)(g_dap[2]+off); d3=*(const float4*)(g_dap[3]+off);
          u0=*(const float4*)(g_hp[0]+off);  u1=*(const float4*)(g_hp[1]+off);
          u2=*(const float4*)(g_hp[2]+off);  u3=*(const float4*)(g_hp[3]+off);
          rb=*(const float4*)(g_k+((size_t)bb*SLEN+(size_t)t*CHK+cc)*D+(size_t)bx*BN+nc);
        }
        FMA_TILE
        __syncthreads();
        if(kt<7){
          sa.x=(d0.x+d1.x+d2.x+d3.x)*silupf(u0.x+u1.x+u2.x+u3.x);
          sa.y=(d0.y+d1.y+d2.y+d3.y)*silupf(u0.y+u1.y+u2.y+u3.y);
          sa.z=(d0.z+d1.z+d2.z+d3.z)*silupf(u0.z+u1.z+u2.z+u3.z);
          sa.w=(d0.w+d1.w+d2.w+d3.w)*silupf(u0.w+u1.w+u2.w+u3.w);
        }
      }
      GEMM_UNPACK
      EPI_STORE(g_g0p[s], by*BM, bx*BN)
    } else if(bid<256){
      const float* W1c=g_W1d[cur]; float* W1n=g_W1d[nxt];
      for(int i4=(bid-128)*256+tid; i4<D*D/4; i4+=128*256){
        float4 m=*(((float4*)g_m1)+i4);
        float4 ga=*(((const float4*)g_g1p[0])+i4);
        float4 gb=*(((const float4*)g_g1p[1])+i4);
        float4 w=*(((const float4*)W1c)+i4);
        m.x=et*m.x-th*(ga.x+gb.x); m.y=et*m.y-th*(ga.y+gb.y);
        m.z=et*m.z-th*(ga.z+gb.z); m.w=et*m.w-th*(ga.w+gb.w);
        float4 wn; wn.x=(1.0f-al)*w.x+m.x; wn.y=(1.0f-al)*w.y+m.y;
        wn.z=(1.0f-al)*w.z+m.z; wn.w=(1.0f-al)*w.w+m.w;
        *(((float4*)g_m1)+i4)=m;
        *(((float4*)W1n)+i4)=wn;
      }
    }
    gsync();

    // ===== P5: W0 update =====
    for(int i4=bid*256+tid; i4<D*D/4; i4+=GRID_P*256){
      float4 m=*(((float4*)g_m0)+i4);
      float4 ga=*(((const float4*)g_g0p[0])+i4);
      float4 gb=*(((const float4*)g_g0p[1])+i4);
      float4 w=*(((float4*)g_W0)+i4);
      m.x=et*m.x-th*(ga.x+gb.x); m.y=et*m.y-th*(ga.y+gb.y);
      m.z=et*m.z-th*(ga.z+gb.z); m.w=et*m.w-th*(ga.w+gb.w);
      w.x=(1.0f-al)*w.x+m.x; w.y=(1.0f-al)*w.y+m.y;
      w.z=(1.0f-al)*w.z+m.z; w.w=(1.0f-al)*w.w+m.w;
      *(((float4*)g_m0)+i4)=m;
      *(((float4*)g_W0)+i4)=w;
    }
    gsync();
  }
}

// ---------------- launch ----------------
extern "C" void kernel_launch(void* const* d_in, const int* in_sizes, int n_in,
                              void* d_out, int out_size)
{
    const float* x    = (const float*)d_in[0];
    const float* Mm   = (const float*)d_in[1];
    const float* memW = (const float*)d_in[2];
    const float* Wk   = (const float*)d_in[3];
    const float* Wv   = (const float*)d_in[4];
    const float* Wq   = (const float*)d_in[5];
    const float* Wout = (const float*)d_in[6];
    const float* Wgd  = (const float*)d_in[7];
    const float* bgd  = (const float*)d_in[8];
    const float* Wgl  = (const float*)d_in[9];
    const float* bgl  = (const float*)d_in[10];
    const float* Wgm  = (const float*)d_in[11];
    const float* bgm  = (const float*)d_in[12];
    const float* gs   = (const float*)d_in[13];
    const float* gr   = (const float*)d_in[14];
    float* outp = (float*)d_out;

    float *p_xs,*p_t,*p_k,*p_v,*p_q,*p_r,*p_cm,*p_gtmp;
    cudaGetSymbolAddress((void**)&p_xs,  g_xs);
    cudaGetSymbolAddress((void**)&p_t,   g_t);
    cudaGetSymbolAddress((void**)&p_k,   g_k);
    cudaGetSymbolAddress((void**)&p_v,   g_v);
    cudaGetSymbolAddress((void**)&p_q,   g_q);
    cudaGetSymbolAddress((void**)&p_r,   g_r);
    cudaGetSymbolAddress((void**)&p_cm,  g_cm);
    cudaGetSymbolAddress((void**)&p_gtmp,g_gtmp);

    // gates
    chunk_mean_k<<<BATCH*NCH, D>>>(x);
    gemm_nt<<<dim3(8,4),256>>>(p_cm, Wgd, bgd, p_gtmp,                 D, 2);
    gemm_nt<<<dim3(8,4),256>>>(p_cm, Wgl, bgl, p_gtmp +   BATCH*NCH*D, D, 2);
    gemm_nt<<<dim3(8,4),256>>>(p_cm, Wgm, bgm, p_gtmp + 2*BATCH*NCH*D, D, 2);
    gate_reduce_k<<<dim3(NCH,3),256>>>();

    // norms + projections
    rmsnorm_k<<<NTOK,256>>>(x, gs, p_xs);
    rmsnorm_k<<<NTOK,256>>>(x, gr, p_t);
    gemm_nt<<<dim3(8,NTOK/BM),256>>>(p_t, Wq, 0, p_q, D, 1);
    l2norm_k<<<NTOK,256>>>(p_q);
    gemm_nn<<<dim3(8,SLEN/BM,BATCH),256>>>(p_xs, Mm, p_t, D,
        (long)SLEN*D, (long)D*D, (long)SLEN*D);
    gemm_nt<<<dim3(8,NTOK/BM),256>>>(p_t, Wk, 0, p_k, D, 1);
    l2norm_k<<<NTOK,256>>>(p_k);
    gemm_nt<<<dim3(8,NTOK/BM),256>>>(p_xs, Wv, 0, p_v, D, 1);

    // init fast weights + momentum
    init_w_k<<<(D*D)/256,256>>>(memW);

    // fused scan
    scan_persist<<<GRID_P,256>>>();

    // final projection
    gemm_nt<<<dim3(8,NTOK/BM),256>>>(p_r, Wout, 0, outp, D, 0);
}